// round 1
// baseline (speedup 1.0000x reference)
#include <cuda_runtime.h>

#define BB 8
#define NN 2048
#define WD 512

// Scratch (device globals: allocation-free, graph-capturable)
__device__ float g_Q[BB * NN * WD];                 // 33.5 MB
__device__ float g_K[BB * NN * WD];                 // 33.5 MB
__device__ float g_E[(size_t)BB * NN * NN];         // 134 MB: exp(S)
__device__ float g_rowsum[BB * NN];
__device__ float g_colsum[BB * NN];

__global__ void zero_sums() {
    int i = blockIdx.x * blockDim.x + threadIdx.x;
    if (i < BB * NN) {
        g_rowsum[i] = 0.f;
        g_colsum[i] = 0.f;
    }
}

// Generic 128x128x16 fp32 tiled GEMM, 256 threads, 8x8 microtile per thread.
// C[row][col] = sum_k A[row][k] * B[col][k]   (logical view)
//   AKC=true : A stored k-contiguous  -> element at A[row*lda + k]
//   AKC=false: A stored row-contiguous-> element at A[k*lda + row]
//   (same convention for B with col/ldb)
// EPI 0: C += bias (aux), store               (linear layers)
// EPI 1: e=exp(c*scale); store E; atomically accumulate row/col sums
// EPI 2: C *= 1/g_rowsum[row], store          (attn1 output)
// EPI 3: C *= 1/g_colsum[row], store          (attn2 output)
template <bool AKC, bool BKC, int EPI>
__global__ void __launch_bounds__(256)
gemm_k(const float* __restrict__ Aall, long aStride, int lda,
       const float* __restrict__ Ball, long bStride, int ldb,
       float* __restrict__ Call, long cStride, int ldc,
       int Ksize,
       const float* __restrict__ aux)
{
    const int tid = threadIdx.x;
    const int tx = tid & 15;
    const int ty = tid >> 4;
    const int bz = blockIdx.z;

    const float* A = Aall + (size_t)bz * aStride;
    const float* Bp = Ball + (size_t)bz * bStride;
    float* C = Call + (size_t)bz * cStride;

    const int row0 = blockIdx.y * 128;
    const int col0 = blockIdx.x * 128;

    __shared__ float sA[16][132];
    __shared__ float sB[16][132];

    float acc[8][8];
#pragma unroll
    for (int i = 0; i < 8; i++)
#pragma unroll
        for (int j = 0; j < 8; j++) acc[i][j] = 0.f;

    for (int kt = 0; kt < Ksize; kt += 16) {
        // ---- load A tile: 128 rows x 16 k ----
#pragma unroll
        for (int t = 0; t < 2; t++) {
            int l = tid * 2 + t;
            if (AKC) {
                int r = l >> 2;
                int kq = (l & 3) << 2;
                float4 v = *reinterpret_cast<const float4*>(
                    A + (size_t)(row0 + r) * lda + (kt + kq));
                sA[kq + 0][r] = v.x;
                sA[kq + 1][r] = v.y;
                sA[kq + 2][r] = v.z;
                sA[kq + 3][r] = v.w;
            } else {
                int k = l >> 5;
                int r4 = (l & 31) << 2;
                float4 v = *reinterpret_cast<const float4*>(
                    A + (size_t)(kt + k) * lda + (row0 + r4));
                *reinterpret_cast<float4*>(&sA[k][r4]) = v;
            }
        }
        // ---- load B tile: 128 cols x 16 k ----
#pragma unroll
        for (int t = 0; t < 2; t++) {
            int l = tid * 2 + t;
            if (BKC) {
                int r = l >> 2;
                int kq = (l & 3) << 2;
                float4 v = *reinterpret_cast<const float4*>(
                    Bp + (size_t)(col0 + r) * ldb + (kt + kq));
                sB[kq + 0][r] = v.x;
                sB[kq + 1][r] = v.y;
                sB[kq + 2][r] = v.z;
                sB[kq + 3][r] = v.w;
            } else {
                int k = l >> 5;
                int r4 = (l & 31) << 2;
                float4 v = *reinterpret_cast<const float4*>(
                    Bp + (size_t)(kt + k) * ldb + (col0 + r4));
                *reinterpret_cast<float4*>(&sB[k][r4]) = v;
            }
        }
        __syncthreads();

#pragma unroll
        for (int k = 0; k < 16; k++) {
            float a[8], b[8];
            *reinterpret_cast<float4*>(a)     = *reinterpret_cast<const float4*>(&sA[k][ty * 8]);
            *reinterpret_cast<float4*>(a + 4) = *reinterpret_cast<const float4*>(&sA[k][ty * 8 + 4]);
            *reinterpret_cast<float4*>(b)     = *reinterpret_cast<const float4*>(&sB[k][tx * 8]);
            *reinterpret_cast<float4*>(b + 4) = *reinterpret_cast<const float4*>(&sB[k][tx * 8 + 4]);
#pragma unroll
            for (int i = 0; i < 8; i++)
#pragma unroll
                for (int j = 0; j < 8; j++)
                    acc[i][j] = fmaf(a[i], b[j], acc[i][j]);
        }
        __syncthreads();
    }

    // ---- epilogues ----
    if constexpr (EPI == 0) {
#pragma unroll
        for (int i = 0; i < 8; i++) {
            int r = row0 + ty * 8 + i;
#pragma unroll
            for (int j = 0; j < 8; j += 4) {
                int c = col0 + tx * 8 + j;
                float4 o;
                o.x = acc[i][j + 0] + aux[c + 0];
                o.y = acc[i][j + 1] + aux[c + 1];
                o.z = acc[i][j + 2] + aux[c + 2];
                o.w = acc[i][j + 3] + aux[c + 3];
                *reinterpret_cast<float4*>(C + (size_t)r * ldc + c) = o;
            }
        }
    } else if constexpr (EPI == 1) {
        const float SC = 0.04419417382415922f;  // 1/sqrt(512)
        float rs[8], cs[8];
#pragma unroll
        for (int i = 0; i < 8; i++) { rs[i] = 0.f; cs[i] = 0.f; }
#pragma unroll
        for (int i = 0; i < 8; i++)
#pragma unroll
            for (int j = 0; j < 8; j++) {
                float e = __expf(acc[i][j] * SC);
                acc[i][j] = e;
                rs[i] += e;
                cs[j] += e;
            }
        // store E
#pragma unroll
        for (int i = 0; i < 8; i++) {
            int r = row0 + ty * 8 + i;
#pragma unroll
            for (int j = 0; j < 8; j += 4) {
                int c = col0 + tx * 8 + j;
                float4 o;
                o.x = acc[i][j + 0];
                o.y = acc[i][j + 1];
                o.z = acc[i][j + 2];
                o.w = acc[i][j + 3];
                *reinterpret_cast<float4*>(C + (size_t)r * ldc + c) = o;
            }
        }
        // row sums: reduce across tx (16 lanes), lanes with tx==0 commit
#pragma unroll
        for (int i = 0; i < 8; i++) {
            float v = rs[i];
            v += __shfl_xor_sync(0xffffffffu, v, 1);
            v += __shfl_xor_sync(0xffffffffu, v, 2);
            v += __shfl_xor_sync(0xffffffffu, v, 4);
            v += __shfl_xor_sync(0xffffffffu, v, 8);
            if (tx == 0)
                atomicAdd(&g_rowsum[bz * NN + row0 + ty * 8 + i], v);
        }
        // col sums: reduce the two ty-halves of each warp, lower half commits
#pragma unroll
        for (int j = 0; j < 8; j++) {
            float v = cs[j];
            v += __shfl_xor_sync(0xffffffffu, v, 16);
            if ((tid & 16) == 0)
                atomicAdd(&g_colsum[bz * NN + col0 + tx * 8 + j], v);
        }
    } else {
#pragma unroll
        for (int i = 0; i < 8; i++) {
            int r = row0 + ty * 8 + i;
            float s;
            if constexpr (EPI == 2)
                s = 1.0f / g_rowsum[bz * NN + r];
            else
                s = 1.0f / g_colsum[bz * NN + r];
#pragma unroll
            for (int j = 0; j < 8; j += 4) {
                int c = col0 + tx * 8 + j;
                float4 o;
                o.x = acc[i][j + 0] * s;
                o.y = acc[i][j + 1] * s;
                o.z = acc[i][j + 2] * s;
                o.w = acc[i][j + 3] * s;
                *reinterpret_cast<float4*>(C + (size_t)r * ldc + c) = o;
            }
        }
    }
}

extern "C" void kernel_launch(void* const* d_in, const int* in_sizes, int n_in,
                              void* d_out, int out_size)
{
    const float* query = (const float*)d_in[0];  // [8,2048,512]
    const float* key   = (const float*)d_in[1];  // [8,2048,512]
    const float* W1    = (const float*)d_in[2];  // [512,512]
    const float* b1    = (const float*)d_in[3];  // [512]
    const float* W2    = (const float*)d_in[4];  // [512,512]
    const float* b2    = (const float*)d_in[5];  // [512]
    float* out = (float*)d_out;                  // [8,4096,512]

    float *Q, *K, *E;
    cudaGetSymbolAddress((void**)&Q, g_Q);
    cudaGetSymbolAddress((void**)&K, g_K);
    cudaGetSymbolAddress((void**)&E, g_E);

    dim3 blk(256);

    // q = query @ W1^T + b1  (M=16384, N=512, K=512; both operands k-contiguous)
    gemm_k<true, true, 0><<<dim3(4, 128, 1), blk>>>(
        query, 0, WD, W1, 0, WD, Q, 0, WD, WD, b1);
    // k = key @ W2^T + b2
    gemm_k<true, true, 0><<<dim3(4, 128, 1), blk>>>(
        key, 0, WD, W2, 0, WD, K, 0, WD, WD, b2);

    zero_sums<<<(BB * NN + 255) / 256, 256>>>();

    // E = exp(Q K^T / sqrt(512)) per batch, plus row/col sums (M=N=2048, K=512)
    gemm_k<true, true, 1><<<dim3(16, 16, BB), blk>>>(
        Q, (long)NN * WD, WD, K, (long)NN * WD, WD,
        E, (long)NN * NN, NN, WD, nullptr);

    // x1 = diag(1/rowsum) E Q   -> out[b, 0:2048, :]
    gemm_k<true, false, 2><<<dim3(4, 16, BB), blk>>>(
        E, (long)NN * NN, NN, Q, (long)NN * WD, WD,
        out, (long)2 * NN * WD, WD, NN, nullptr);

    // x2 = diag(1/colsum) E^T K -> out[b, 2048:4096, :]
    gemm_k<false, false, 3><<<dim3(4, 16, BB), blk>>>(
        E, (long)NN * NN, NN, K, (long)NN * WD, WD,
        out + (size_t)NN * WD, (long)2 * NN * WD, WD, NN, nullptr);
}